// round 4
// baseline (speedup 1.0000x reference)
#include <cuda_runtime.h>

#define D   48
#define NN  100000
#define NE  1600000
#define NL  6
#define NG  1000

__device__ __align__(16) float g_h[NN * D];
__device__ __align__(16) float g_agg[NN * D];

typedef unsigned long long u64;

__device__ __forceinline__ u64 pack2(float v) {
    u64 r; asm("mov.b64 %0, {%1, %1};" : "=l"(r) : "f"(v)); return r;
}
__device__ __forceinline__ void unpack2(u64 v, float& lo, float& hi) {
    asm("mov.b64 {%0, %1}, %2;" : "=f"(lo), "=f"(hi) : "l"(v));
}
__device__ __forceinline__ u64 ffma2(u64 a, u64 b, u64 c) {
    u64 d; asm("fma.rn.f32x2 %0, %1, %2, %3;" : "=l"(d) : "l"(a), "l"(b), "l"(c));
    return d;
}

// r[48] = relu(x[48] @ w1[48x48] + b1[48]); weights row-major (i, k), k contiguous
__device__ __forceinline__ void mlp_hidden(const float* x, const float* s_w1,
                                           const float* s_b1, float* r) {
    u64 acc[24];
    const u64* bp = (const u64*)s_b1;
#pragma unroll
    for (int k = 0; k < 24; k++) acc[k] = bp[k];
#pragma unroll
    for (int i = 0; i < D; i++) {
        u64 xx = pack2(x[i]);
        const ulonglong2* w = (const ulonglong2*)(s_w1 + i * D);
#pragma unroll
        for (int k = 0; k < 12; k++) {
            ulonglong2 ww = w[k];
            acc[2 * k]     = ffma2(xx, ww.x, acc[2 * k]);
            acc[2 * k + 1] = ffma2(xx, ww.y, acc[2 * k + 1]);
        }
    }
#pragma unroll
    for (int k = 0; k < 24; k++) {
        float lo, hi; unpack2(acc[k], lo, hi);
        r[2 * k]     = fmaxf(lo, 0.f);
        r[2 * k + 1] = fmaxf(hi, 0.f);
    }
}

// m[48] = r[48] @ w2[48x48] + b2[48]
__device__ __forceinline__ void mlp_out(const float* r, const float* s_w2,
                                        const float* s_b2, float* m) {
    u64 acc[24];
    const u64* bp = (const u64*)s_b2;
#pragma unroll
    for (int k = 0; k < 24; k++) acc[k] = bp[k];
#pragma unroll
    for (int i = 0; i < D; i++) {
        u64 xx = pack2(r[i]);
        const ulonglong2* w = (const ulonglong2*)(s_w2 + i * D);
#pragma unroll
        for (int k = 0; k < 12; k++) {
            ulonglong2 ww = w[k];
            acc[2 * k]     = ffma2(xx, ww.x, acc[2 * k]);
            acc[2 * k + 1] = ffma2(xx, ww.y, acc[2 * k + 1]);
        }
    }
#pragma unroll
    for (int k = 0; k < 24; k++) unpack2(acc[k], m[2 * k], m[2 * k + 1]);
}

__global__ void __launch_bounds__(128) embed_kernel(const int* __restrict__ an,
                                                    const float* __restrict__ emb) {
    int n = blockIdx.x * 128 + threadIdx.x;
    if (n >= NN) return;
    const float4* e = (const float4*)(emb + (size_t)an[n] * D);
    float4* hp = (float4*)(g_h + (size_t)n * D);
#pragma unroll
    for (int q = 0; q < 12; q++) hp[q] = e[q];
}

__global__ void __launch_bounds__(256) zero_agg_kernel() {
    int t = blockIdx.x * 256 + threadIdx.x;
    if (t < NN * D / 4) ((float4*)g_agg)[t] = make_float4(0.f, 0.f, 0.f, 0.f);
}

__global__ void __launch_bounds__(256) zero_out_kernel(float* out) {
    int t = blockIdx.x * 256 + threadIdx.x;
    if (t < NG) out[t] = 0.f;
}

__global__ void __launch_bounds__(128) edge_kernel(const int* __restrict__ edge,
                                                   const float* __restrict__ w1,
                                                   const float* __restrict__ b1,
                                                   const float* __restrict__ w2,
                                                   const float* __restrict__ b2) {
    __shared__ __align__(16) float s_w1[D * D];
    __shared__ __align__(16) float s_w2[D * D];
    __shared__ __align__(16) float s_b1[D];
    __shared__ __align__(16) float s_b2[D];
    for (int t = threadIdx.x; t < D * D; t += 128) { s_w1[t] = w1[t]; s_w2[t] = w2[t]; }
    if (threadIdx.x < D) { s_b1[threadIdx.x] = b1[threadIdx.x]; s_b2[threadIdx.x] = b2[threadIdx.x]; }
    __syncthreads();

    int e = blockIdx.x * 128 + threadIdx.x;
    if (e >= NE) return;
    int src = edge[e];
    int dst = edge[NE + e];

    const float4* hs = (const float4*)(g_h + (size_t)src * D);
    const float4* hd = (const float4*)(g_h + (size_t)dst * D);
    float x[D];
#pragma unroll
    for (int q = 0; q < 12; q++) {
        float4 a = hs[q], b = hd[q];
        x[4 * q + 0] = a.x * b.x; x[4 * q + 1] = a.y * b.y;
        x[4 * q + 2] = a.z * b.z; x[4 * q + 3] = a.w * b.w;
    }

    float r[D], m[D];
    mlp_hidden(x, s_w1, s_b1, r);
    mlp_out(r, s_w2, s_b2, m);

    float* aggp = g_agg + (size_t)dst * D;
#pragma unroll
    for (int q = 0; q < 12; q++) {
        asm volatile("red.global.add.v4.f32 [%0], {%1, %2, %3, %4};"
                     :: "l"(aggp + 4 * q),
                        "f"(m[4 * q + 0]), "f"(m[4 * q + 1]),
                        "f"(m[4 * q + 2]), "f"(m[4 * q + 3])
                     : "memory");
    }
}

__global__ void __launch_bounds__(128) update_kernel(const float* __restrict__ w1,
                                                     const float* __restrict__ b1,
                                                     const float* __restrict__ w2,
                                                     const float* __restrict__ b2) {
    __shared__ __align__(16) float s_w1[D * D];
    __shared__ __align__(16) float s_w2[D * D];
    __shared__ __align__(16) float s_b1[D];
    __shared__ __align__(16) float s_b2[D];
    for (int t = threadIdx.x; t < D * D; t += 128) { s_w1[t] = w1[t]; s_w2[t] = w2[t]; }
    if (threadIdx.x < D) { s_b1[threadIdx.x] = b1[threadIdx.x]; s_b2[threadIdx.x] = b2[threadIdx.x]; }
    __syncthreads();

    int n = blockIdx.x * 128 + threadIdx.x;
    if (n >= NN) return;

    const float4* ap = (const float4*)(g_agg + (size_t)n * D);
    float x[D];
#pragma unroll
    for (int q = 0; q < 12; q++) {
        float4 a = ap[q];
        x[4 * q + 0] = a.x; x[4 * q + 1] = a.y; x[4 * q + 2] = a.z; x[4 * q + 3] = a.w;
    }

    float r[D], u[D];
    mlp_hidden(x, s_w1, s_b1, r);
    mlp_out(r, s_w2, s_b2, u);

    float4* hp = (float4*)(g_h + (size_t)n * D);
#pragma unroll
    for (int q = 0; q < 12; q++) {
        float4 hv = hp[q];
        hv.x += u[4 * q + 0]; hv.y += u[4 * q + 1];
        hv.z += u[4 * q + 2]; hv.w += u[4 * q + 3];
        hp[q] = hv;
    }
}

__global__ void __launch_bounds__(128) readout_kernel(const float* __restrict__ w1,
                                                      const float* __restrict__ b1,
                                                      const float* __restrict__ w2v,
                                                      const float* __restrict__ b2s,
                                                      const int* __restrict__ gid,
                                                      float* __restrict__ out) {
    __shared__ __align__(16) float s_w1[D * D];
    __shared__ __align__(16) float s_b1[D];
    __shared__ __align__(16) float s_w2[D];
    __shared__ float s_b2;
    for (int t = threadIdx.x; t < D * D; t += 128) s_w1[t] = w1[t];
    if (threadIdx.x < D) { s_b1[threadIdx.x] = b1[threadIdx.x]; s_w2[threadIdx.x] = w2v[threadIdx.x]; }
    if (threadIdx.x == 0) s_b2 = b2s[0];
    __syncthreads();

    int n = blockIdx.x * 128 + threadIdx.x;
    if (n >= NN) return;

    const float4* hp = (const float4*)(g_h + (size_t)n * D);
    float x[D];
#pragma unroll
    for (int q = 0; q < 12; q++) {
        float4 a = hp[q];
        x[4 * q + 0] = a.x; x[4 * q + 1] = a.y; x[4 * q + 2] = a.z; x[4 * q + 3] = a.w;
    }

    float r[D];
    mlp_hidden(x, s_w1, s_b1, r);

    float y = s_b2;
#pragma unroll
    for (int k = 0; k < D; k++) y += r[k] * s_w2[k];

    atomicAdd(&out[gid[n]], y);
}

extern "C" void kernel_launch(void* const* d_in, const int* in_sizes, int n_in,
                              void* d_out, int out_size) {
    const int*   AtomicNum = (const int*)d_in[0];
    const int*   Edge      = (const int*)d_in[1];
    const int*   graph_id  = (const int*)d_in[2];
    const float* emb       = (const float*)d_in[3];
    const float* msg_w1    = (const float*)d_in[4];
    const float* msg_b1    = (const float*)d_in[5];
    const float* msg_w2    = (const float*)d_in[6];
    const float* msg_b2    = (const float*)d_in[7];
    const float* upd_w1    = (const float*)d_in[8];
    const float* upd_b1    = (const float*)d_in[9];
    const float* upd_w2    = (const float*)d_in[10];
    const float* upd_b2    = (const float*)d_in[11];
    const float* ro_w1     = (const float*)d_in[12];
    const float* ro_b1     = (const float*)d_in[13];
    const float* ro_w2     = (const float*)d_in[14];
    const float* ro_b2     = (const float*)d_in[15];
    float* out = (float*)d_out;

    embed_kernel<<<(NN + 127) / 128, 128>>>(AtomicNum, emb);

    const int zero_blocks = (NN * D / 4 + 255) / 256;
    const int edge_blocks = (NE + 127) / 128;
    const int node_blocks = (NN + 127) / 128;

    for (int l = 0; l < NL; l++) {
        zero_agg_kernel<<<zero_blocks, 256>>>();
        edge_kernel<<<edge_blocks, 128>>>(Edge,
                                          msg_w1 + (size_t)l * D * D, msg_b1 + (size_t)l * D,
                                          msg_w2 + (size_t)l * D * D, msg_b2 + (size_t)l * D);
        update_kernel<<<node_blocks, 128>>>(upd_w1 + (size_t)l * D * D, upd_b1 + (size_t)l * D,
                                            upd_w2 + (size_t)l * D * D, upd_b2 + (size_t)l * D);
    }

    zero_out_kernel<<<(NG + 255) / 256, 256>>>(out);
    readout_kernel<<<node_blocks, 128>>>(ro_w1, ro_b1, ro_w2, ro_b2, graph_id, out);
}